// round 2
// baseline (speedup 1.0000x reference)
#include <cuda_runtime.h>
#include <cstdint>

// YOLO detection postprocess:
//   in : (16, 25200, 85) f32   [xc, yc, w, h, conf, cls0..cls79]
//   out: (16, 25200, 6)  f32   [xmin, ymin, xmax, ymax, conf*maxcls, argmax] or zeros
// One warp per row. Coalesced loads (lane, lane+32, lane+64), warp shuffle
// max+argmax reduction with first-index tie-break.

#define CONF_THRESH 0.25f
#define ROW_LEN 85
#define OUT_LEN 6

__global__ __launch_bounds__(256) void yolo_post_kernel(
    const float* __restrict__ in, float* __restrict__ out, int nrows)
{
    const int gwarp = (blockIdx.x * blockDim.x + threadIdx.x) >> 5;
    const int lane  = threadIdx.x & 31;
    if (gwarp >= nrows) return;

    const float* row = in + (size_t)gwarp * ROW_LEN;

    float x = 0.f, y = 0.f, w = 0.f, h = 0.f, conf = 0.f;
    float best = -3.402823466e+38f;
    int   bidx = 0x7fffffff;

#pragma unroll
    for (int k = 0; k < 3; k++) {
        const int e = lane + k * 32;
        if (e < ROW_LEN) {
            const float v = __ldg(row + e);
            if (e == 0)      x = v;
            else if (e == 1) y = v;
            else if (e == 2) w = v;
            else if (e == 3) h = v;
            else if (e == 4) conf = v;
            else {
                // class score; ascending e per lane -> first-max kept on ties
                if (v > best) { best = v; bidx = e - 5; }
            }
        }
    }

    // Warp reduction: max value, tie -> lowest class index (matches jnp.argmax)
#pragma unroll
    for (int off = 16; off > 0; off >>= 1) {
        const float ob = __shfl_down_sync(0xffffffffu, best, off);
        const int   oi = __shfl_down_sync(0xffffffffu, bidx, off);
        if (ob > best || (ob == best && oi < bidx)) { best = ob; bidx = oi; }
    }

    // Gather scalars held by specific lanes
    const float X = __shfl_sync(0xffffffffu, x,    0);
    const float Y = __shfl_sync(0xffffffffu, y,    1);
    const float W = __shfl_sync(0xffffffffu, w,    2);
    const float H = __shfl_sync(0xffffffffu, h,    3);
    const float C = __shfl_sync(0xffffffffu, conf, 4);
    best = __shfl_sync(0xffffffffu, best, 0);
    bidx = __shfl_sync(0xffffffffu, bidx, 0);

    const float score = C * best;
    const bool  keep  = score > CONF_THRESH;

    float o;
    switch (lane) {
        case 0: o = X - 0.5f * W; break;
        case 1: o = Y - 0.5f * H; break;
        case 2: o = X + 0.5f * W; break;
        case 3: o = Y + 0.5f * H; break;
        case 4: o = score;        break;
        case 5: o = (float)bidx;  break;
        default: o = 0.f;         break;
    }

    if (lane < OUT_LEN)
        out[(size_t)gwarp * OUT_LEN + lane] = keep ? o : 0.0f;
}

extern "C" void kernel_launch(void* const* d_in, const int* in_sizes, int n_in,
                              void* d_out, int out_size)
{
    const float* in  = (const float*)d_in[0];
    float*       out = (float*)d_out;

    const int nrows = in_sizes[0] / ROW_LEN;   // 16*25200 = 403200
    const int warps_per_block = 256 / 32;      // 8
    const int blocks = (nrows + warps_per_block - 1) / warps_per_block;

    yolo_post_kernel<<<blocks, 256>>>(in, out, nrows);
}

// round 5
// speedup vs baseline: 4.9091x; 4.9091x over previous
#include <cuda_runtime.h>
#include <cstdint>

// YOLO detection postprocess:
//   in : (16, 25200, 85) f32   [xc, yc, w, h, conf, cls0..cls79]
//   out: (16, 25200, 6)  f32   [xmin, ymin, xmax, ymax, conf*maxcls, argmax] or zeros
//
// Block = 128 threads, processes 128 rows:
//   phase 1: coalesced float4 loads -> static smem tile (43520 B, 16B aligned)
//   phase 2: thread t processes row t entirely from smem (stride 85 = odd
//            -> conflict-free banks), no shuffles, then 3x STG.64 output.

#define CONF_THRESH 0.25f
#define ROW_LEN 85
#define OUT_LEN 6
#define ROWS_PER_BLOCK 128
#define THREADS 128
#define TILE_FLOATS (ROWS_PER_BLOCK * ROW_LEN)        // 10880
#define TILE_VEC4   (TILE_FLOATS / 4)                 // 2720

__global__ __launch_bounds__(THREADS) void yolo_post_kernel(
    const float* __restrict__ in, float* __restrict__ out, int nrows)
{
    __shared__ float tile[TILE_FLOATS];

    const int tid = threadIdx.x;
    const int row0 = blockIdx.x * ROWS_PER_BLOCK;

    // ---- Phase 1: coalesced vectorized load of 128 rows into smem ----
    // Tile byte offset = blockIdx.x * 43520, which is 16B-aligned.
    {
        const float4* src = reinterpret_cast<const float4*>(in + (size_t)row0 * ROW_LEN);
        float4* dst = reinterpret_cast<float4*>(tile);
#pragma unroll
        for (int i = 0; i < TILE_VEC4 / THREADS; i++)        // 21 full iterations
            dst[tid + i * THREADS] = src[tid + i * THREADS];
        // remainder: 2720 - 21*128 = 32 vectors
        if (tid < TILE_VEC4 - (TILE_VEC4 / THREADS) * THREADS)
            dst[tid + (TILE_VEC4 / THREADS) * THREADS] =
                src[tid + (TILE_VEC4 / THREADS) * THREADS];
    }
    __syncthreads();

    // ---- Phase 2: one thread per row, all reads from smem ----
    const float* r = tile + tid * ROW_LEN;

    const float x = r[0];
    const float y = r[1];
    const float w = r[2];
    const float h = r[3];
    const float conf = r[4];

    float best = r[5];
    int   bidx = 0;
#pragma unroll 4
    for (int c = 1; c < 80; c++) {
        const float v = r[5 + c];
        if (v > best) { best = v; bidx = c; }   // strict > keeps first max (jnp.argmax)
    }

    const float score = conf * best;
    const bool  keep  = score > CONF_THRESH;

    const float hw = 0.5f * w;
    const float hh = 0.5f * h;

    float2 o0, o1, o2;
    if (keep) {
        o0 = make_float2(x - hw, y - hh);
        o1 = make_float2(x + hw, y + hh);
        o2 = make_float2(score, (float)bidx);
    } else {
        o0 = make_float2(0.f, 0.f);
        o1 = make_float2(0.f, 0.f);
        o2 = make_float2(0.f, 0.f);
    }

    // out row base byte offset = 24 * (row0 + tid): 8B aligned -> float2 stores
    float2* orow = reinterpret_cast<float2*>(out + (size_t)(row0 + tid) * OUT_LEN);
    orow[0] = o0;
    orow[1] = o1;
    orow[2] = o2;
}

extern "C" void kernel_launch(void* const* d_in, const int* in_sizes, int n_in,
                              void* d_out, int out_size)
{
    const float* in  = (const float*)d_in[0];
    float*       out = (float*)d_out;

    const int nrows = in_sizes[0] / ROW_LEN;          // 403200
    const int blocks = nrows / ROWS_PER_BLOCK;        // 3150 (exact)

    yolo_post_kernel<<<blocks, THREADS>>>(in, out, nrows);
}